// round 1
// baseline (speedup 1.0000x reference)
#include <cuda_runtime.h>
#include <cstdint>

#define COLS     16384
#define KSEL     256
#define NTHREADS 512
#define VPT      8        // float4 per thread: 512*8*4 = 16384 elements
#define CAP      2048     // candidate list capacity
#define SCAP     512      // final-window list capacity

// monotone float->uint key: larger float => larger key
__device__ __forceinline__ unsigned f2k(float f) {
    unsigned u = __float_as_uint(f);
    return u ^ ((unsigned)((int)u >> 31) | 0x80000000u);
}
// recover relu(value) from key (negatives and +/-0 -> 0)
__device__ __forceinline__ float k2relu(unsigned k) {
    return (k > 0x80000000u) ? __uint_as_float(k ^ 0x80000000u) : 0.0f;
}

__global__ void __launch_bounds__(NTHREADS, 2)
topk_kernel(const float* __restrict__ x, float* __restrict__ out)
{
    __shared__ unsigned sk[CAP];               // candidate keys
    __shared__ unsigned si[CAP];               // candidate column indices
    __shared__ unsigned long long slist[SCAP]; // final window composites
    __shared__ unsigned hist[8];
    __shared__ unsigned s_cnt, s_kmax, s_m;

    const int tid  = threadIdx.x;
    const int lane = tid & 31;
    const size_t row = blockIdx.x;
    const float4* __restrict__ xr4   = reinterpret_cast<const float4*>(x + row * COLS);
    float*        __restrict__ orow  = out + row * COLS;
    float4*       __restrict__ orow4 = reinterpret_cast<float4*>(orow);

    // ---- 1) zero-fill the output row (streaming; overlaps with the scan) ----
    float4 z = make_float4(0.f, 0.f, 0.f, 0.f);
    #pragma unroll
    for (int i = 0; i < VPT; i++) orow4[tid + i * NTHREADS] = z;

    // ---- 2) candidate-collection scan with adaptive threshold ----
    unsigned kT  = f2k(1.9f);          // pre-filter: ~470 expected candidates for N(0,1)
    unsigned aLo = 0u, bHi = 0xFFFFFFFFu;
    unsigned C = 0, kmax = 0;

    for (int attempt = 0; attempt < 34; attempt++) {
        if (tid == 0) { s_cnt = 0; s_kmax = 0; }
        __syncthreads();

        unsigned mymax = 0;
        #pragma unroll
        for (int i = 0; i < VPT; i++) {
            float4 v = xr4[tid + i * NTHREADS];
            unsigned k0 = f2k(v.x), k1 = f2k(v.y), k2 = f2k(v.z), k3 = f2k(v.w);
            mymax = max(mymax, max(max(k0, k1), max(k2, k3)));

            unsigned b0 = __ballot_sync(0xFFFFFFFFu, k0 >= kT);
            unsigned b1 = __ballot_sync(0xFFFFFFFFu, k1 >= kT);
            unsigned b2 = __ballot_sync(0xFFFFFFFFu, k2 >= kT);
            unsigned b3 = __ballot_sync(0xFFFFFFFFu, k3 >= kT);
            unsigned tot = __popc(b0) + __popc(b1) + __popc(b2) + __popc(b3);
            if (tot) {  // one smem atomic per 128 elements (warp-aggregated)
                unsigned base = 0;
                if (lane == 0) base = atomicAdd(&s_cnt, tot);
                base = __shfl_sync(0xFFFFFFFFu, base, 0);
                unsigned lt   = (1u << lane) - 1u;
                unsigned idx0 = 4u * (unsigned)(tid + i * NTHREADS);
                unsigned p;
                if (k0 >= kT) { p = base + __popc(b0 & lt); if (p < CAP) { sk[p] = k0; si[p] = idx0;     } }
                base += __popc(b0);
                if (k1 >= kT) { p = base + __popc(b1 & lt); if (p < CAP) { sk[p] = k1; si[p] = idx0 + 1; } }
                base += __popc(b1);
                if (k2 >= kT) { p = base + __popc(b2 & lt); if (p < CAP) { sk[p] = k2; si[p] = idx0 + 2; } }
                base += __popc(b2);
                if (k3 >= kT) { p = base + __popc(b3 & lt); if (p < CAP) { sk[p] = k3; si[p] = idx0 + 3; } }
            }
        }
        #pragma unroll
        for (int off = 16; off; off >>= 1)
            mymax = max(mymax, __shfl_down_sync(0xFFFFFFFFu, mymax, off));
        if (lane == 0) atomicMax(&s_kmax, mymax);
        __syncthreads();

        C = s_cnt; kmax = s_kmax;
        if (C >= KSEL && C <= CAP) break;   // normal path: first attempt succeeds
        if (C > CAP) aLo = kT; else bHi = kT;   // binary search threshold (robust fallback)
        unsigned nkT = aLo + ((bHi - aLo) >> 1);
        if (nkT == kT) break;
        kT = nkT;
        __syncthreads();   // everyone has read s_cnt/s_kmax before reset
    }
    if (C > CAP) C = CAP;

    // ---- 3) own candidates in registers ----
    unsigned ok[CAP / NTHREADS], oi[CAP / NTHREADS];
    int nown = 0;
    for (unsigned p = tid; p < C; p += NTHREADS) { ok[nown] = sk[p]; oi[nown] = si[p]; nown++; }

    unsigned winLo = kT;
    unsigned winHi = kmax + 1u;   // exclusive upper bound (> all candidate keys)
    unsigned need  = KSEL;
    if (need > C) need = C;       // pathological guard

    // ---- 4) 8-way key-space narrowing rounds (register counters, tiny atomics) ----
    for (int r = 0; r < 4; r++) {
        unsigned span = winHi - winLo;
        if (span < 16u) break;
        unsigned step = span >> 3;

        if (tid < 8) hist[tid] = 0;
        __syncthreads();

        unsigned c[8] = {0,0,0,0,0,0,0,0};
        for (int q = 0; q < nown; q++) {
            unsigned k = ok[q];
            if (k < winHi) {
                #pragma unroll
                for (int j = 0; j < 8; j++) c[j] += (k >= winLo + (unsigned)j * step);
            }
        }
        #pragma unroll
        for (int j = 0; j < 8; j++) {
            unsigned v = c[j];
            #pragma unroll
            for (int off = 16; off; off >>= 1) v += __shfl_down_sync(0xFFFFFFFFu, v, off);
            if (lane == 0 && v) atomicAdd(&hist[j], v);
        }
        __syncthreads();

        unsigned n[8];
        #pragma unroll
        for (int j = 0; j < 8; j++) n[j] = hist[j];
        __syncthreads();   // reads done before next round re-zeroes hist

        int js = 7;
        while (js > 0 && n[js] < need) js--;
        unsigned nAbove = (js < 7) ? n[js + 1] : 0u;
        unsigned newLo  = winLo + (unsigned)js * step;
        unsigned newHi  = (js == 7) ? winHi : (winLo + (unsigned)(js + 1) * step);
        need -= nAbove;            // everything >= newHi is selected
        winLo = newLo; winHi = newHi;
        if (n[js] - nAbove <= 48u) break;   // small enough for exact rank
    }

    // ---- 5) gather final window; exact stable rank via (key, ~idx) composite ----
    if (tid == 0) s_m = 0;
    __syncthreads();
    for (int q = 0; q < nown; q++) {
        unsigned k = ok[q];
        if (k >= winLo && k < winHi) {
            unsigned p = atomicAdd(&s_m, 1u);
            if (p < SCAP)
                slist[p] = ((unsigned long long)k << 32) | (unsigned)(~oi[q]);
        }
    }
    __syncthreads();
    unsigned m = s_m; if (m > SCAP) m = SCAP;

    // rank: higher key first, lower index first on ties (matches jax top_k)
    for (unsigned p = tid; p < m; p += NTHREADS) {
        unsigned long long mine = slist[p];
        unsigned rnk = 0;
        for (unsigned j = 0; j < m; j++) rnk += (slist[j] > mine);
        if (rnk < need) {
            unsigned k   = (unsigned)(mine >> 32);
            unsigned idx = ~(unsigned)mine;
            orow[idx] = k2relu(k);
        }
    }
    // everything above the final window is selected unconditionally
    for (int q = 0; q < nown; q++) {
        if (ok[q] >= winHi) orow[oi[q]] = k2relu(ok[q]);
    }
}

extern "C" void kernel_launch(void* const* d_in, const int* in_sizes, int n_in,
                              void* d_out, int out_size) {
    const float* x = (const float*)d_in[0];
    float* out = (float*)d_out;
    int rows = in_sizes[0] / COLS;
    topk_kernel<<<rows, NTHREADS>>>(x, out);
}

// round 2
// speedup vs baseline: 1.3215x; 1.3215x over previous
#include <cuda_runtime.h>
#include <cstdint>

#define COLS 16384
#define KSEL 256
#define NT   512
#define VPT  8            // float4 per thread: 512*8*4 = 16384
#define CAP  2048
#define NOWN (CAP / NT)   // 4

typedef unsigned long long u64;

// monotone float->uint key: larger float => larger key
__device__ __forceinline__ unsigned f2k(float f) {
    unsigned u = __float_as_uint(f);
    return u ^ ((unsigned)((int)u >> 31) | 0x80000000u);
}
// inverse of f2k
__device__ __forceinline__ float k2f(unsigned k) {
    unsigned u = (k & 0x80000000u) ? (k ^ 0x80000000u) : ~k;
    return __uint_as_float(u);
}
// recover relu(value) from key
__device__ __forceinline__ float k2relu(unsigned k) {
    return (k > 0x80000000u) ? __uint_as_float(k ^ 0x80000000u) : 0.0f;
}

__global__ void __launch_bounds__(NT, 2)
topk_kernel(const float* __restrict__ x, float* __restrict__ out)
{
    __shared__ u64 cand[CAP];          // candidate (key<<32 | ~idx); reused as final window
    __shared__ unsigned hist[32];      // 8 buckets x 4 rounds (pre-zeroed once)
    __shared__ unsigned s_cnt, s_kmax, s_m;

    const int tid  = threadIdx.x;
    const int lane = tid & 31;
    const size_t row = blockIdx.x;
    const float4* __restrict__ xr4   = reinterpret_cast<const float4*>(x + row * COLS);
    float*        __restrict__ orow  = out + row * COLS;
    float4*       __restrict__ orow4 = reinterpret_cast<float4*>(orow);

    if (tid == 0) { s_cnt = 0; s_kmax = 0; s_m = 0; }
    if (tid < 32) hist[tid] = 0;

    // ---- 1) front-batch ALL loads (MLP=8/warp), then stream the zero-fill ----
    float4 v[VPT];
    #pragma unroll
    for (int i = 0; i < VPT; i++) v[i] = xr4[tid + i * NT];

    float4 z = make_float4(0.f, 0.f, 0.f, 0.f);
    #pragma unroll
    for (int i = 0; i < VPT; i++) orow4[tid + i * NT] = z;

    __syncthreads();   // s_cnt/hist zeroed before any push

    // ---- 2) filter in float domain; rare predicated pushes; no ballots ----
    const float T0 = 1.9f;     // ~470 expected candidates/row for N(0,1)
    float fm = -__int_as_float(0x7f800000);  // -inf
    #pragma unroll
    for (int i = 0; i < VPT; i++) {
        float4 w = v[i];
        fm = fmaxf(fm, fmaxf(fmaxf(w.x, w.y), fmaxf(w.z, w.w)));
        unsigned idx0 = 4u * (unsigned)(tid + i * NT);
        if (w.x >= T0) { unsigned p = atomicAdd(&s_cnt, 1u); if (p < CAP) cand[p] = ((u64)f2k(w.x) << 32) | (unsigned)~(idx0);      }
        if (w.y >= T0) { unsigned p = atomicAdd(&s_cnt, 1u); if (p < CAP) cand[p] = ((u64)f2k(w.y) << 32) | (unsigned)~(idx0 + 1u); }
        if (w.z >= T0) { unsigned p = atomicAdd(&s_cnt, 1u); if (p < CAP) cand[p] = ((u64)f2k(w.z) << 32) | (unsigned)~(idx0 + 2u); }
        if (w.w >= T0) { unsigned p = atomicAdd(&s_cnt, 1u); if (p < CAP) cand[p] = ((u64)f2k(w.w) << 32) | (unsigned)~(idx0 + 3u); }
    }
    #pragma unroll
    for (int off = 16; off; off >>= 1)
        fm = fmaxf(fm, __shfl_down_sync(0xFFFFFFFFu, fm, off));
    if (lane == 0) atomicMax(&s_kmax, f2k(fm));
    __syncthreads();

    unsigned C = s_cnt, kmax = s_kmax;
    unsigned kT = f2k(T0);

    // ---- 3) rare fallback: binary-search threshold, rescanning REGISTERS ----
    if (C < KSEL || C > CAP) {
        unsigned aLo = 0u, bHi = 0xFFFFFFFFu;
        if (C > CAP) aLo = kT; else bHi = kT;
        for (int it = 0; it < 33; it++) {
            unsigned nkT = aLo + ((bHi - aLo) >> 1);
            if (nkT == kT) break;
            kT = nkT;
            float Tf = k2f(kT);
            __syncthreads();
            if (tid == 0) s_cnt = 0;
            __syncthreads();
            #pragma unroll
            for (int i = 0; i < VPT; i++) {
                float4 w = v[i];
                unsigned idx0 = 4u * (unsigned)(tid + i * NT);
                if (w.x >= Tf) { unsigned p = atomicAdd(&s_cnt, 1u); if (p < CAP) cand[p] = ((u64)f2k(w.x) << 32) | (unsigned)~(idx0);      }
                if (w.y >= Tf) { unsigned p = atomicAdd(&s_cnt, 1u); if (p < CAP) cand[p] = ((u64)f2k(w.y) << 32) | (unsigned)~(idx0 + 1u); }
                if (w.z >= Tf) { unsigned p = atomicAdd(&s_cnt, 1u); if (p < CAP) cand[p] = ((u64)f2k(w.z) << 32) | (unsigned)~(idx0 + 2u); }
                if (w.w >= Tf) { unsigned p = atomicAdd(&s_cnt, 1u); if (p < CAP) cand[p] = ((u64)f2k(w.w) << 32) | (unsigned)~(idx0 + 3u); }
            }
            __syncthreads();
            C = s_cnt;
            if (C >= KSEL && C <= CAP) break;
            if (C > CAP) aLo = kT; else bHi = kT;
        }
        if (C > CAP) C = CAP;
    }

    // ---- 4) own candidates in registers ----
    u64 oc[NOWN];
    int nown = 0;
    for (unsigned p = tid; p < C; p += NT) { oc[nown] = cand[p]; nown++; }
    __syncthreads();   // all reads of cand[] done before it is reused below

    unsigned winLo = kT;
    unsigned winHi = kmax + 1u;
    unsigned need  = (KSEL < C) ? KSEL : C;

    // ---- 5) 8-way key-space narrowing (1 sync/round via pre-zeroed hist banks) ----
    for (int r = 0; r < 4; r++) {
        unsigned span = winHi - winLo;
        if (span < 16u) break;
        unsigned step = span >> 3;
        unsigned* hb = &hist[8 * r];

        unsigned c[8] = {0,0,0,0,0,0,0,0};
        for (int q = 0; q < nown; q++) {
            unsigned k = (unsigned)(oc[q] >> 32);
            if (k < winHi) {
                #pragma unroll
                for (int j = 0; j < 8; j++) c[j] += (k >= winLo + (unsigned)j * step);
            }
        }
        #pragma unroll
        for (int j = 0; j < 8; j++) {
            unsigned s = c[j];
            #pragma unroll
            for (int off = 16; off; off >>= 1) s += __shfl_down_sync(0xFFFFFFFFu, s, off);
            if (lane == 0 && s) atomicAdd(&hb[j], s);
        }
        __syncthreads();

        unsigned n[8];
        #pragma unroll
        for (int j = 0; j < 8; j++) n[j] = hb[j];

        int js = 7;
        while (js > 0 && n[js] < need) js--;
        unsigned nAbove = (js < 7) ? n[js + 1] : 0u;
        winHi = (js == 7) ? winHi : (winLo + (unsigned)(js + 1) * step);
        winLo = winLo + (unsigned)js * step;
        need -= nAbove;
        if (n[js] - nAbove <= 48u) break;
    }

    // ---- 6) gather final window into cand[] (reused); exact stable rank ----
    for (int q = 0; q < nown; q++) {
        unsigned k = (unsigned)(oc[q] >> 32);
        if (k >= winLo && k < winHi) {
            unsigned p = atomicAdd(&s_m, 1u);
            if (p < CAP) cand[p] = oc[q];
        }
    }
    __syncthreads();
    unsigned m = s_m; if (m > CAP) m = CAP;

    // higher key first; lower index first on ties (low word is ~idx)
    for (unsigned p = tid; p < m; p += NT) {
        u64 mine = cand[p];
        unsigned rnk = 0;
        for (unsigned j = 0; j < m; j++) rnk += (cand[j] > mine);
        if (rnk < need) {
            unsigned k   = (unsigned)(mine >> 32);
            unsigned idx = ~(unsigned)mine;
            orow[idx] = k2relu(k);
        }
    }
    // everything above the final window is selected unconditionally
    for (int q = 0; q < nown; q++) {
        unsigned k = (unsigned)(oc[q] >> 32);
        if (k >= winHi) orow[~(unsigned)oc[q]] = k2relu(k);
    }
}

extern "C" void kernel_launch(void* const* d_in, const int* in_sizes, int n_in,
                              void* d_out, int out_size) {
    const float* x = (const float*)d_in[0];
    float* out = (float*)d_out;
    int rows = in_sizes[0] / COLS;
    topk_kernel<<<rows, NT>>>(x, out);
}